// round 17
// baseline (speedup 1.0000x reference)
#include <cuda_runtime.h>

#define IMG_W 512
#define IMG_H 512
#define NBATCH 32
#define RSTRIP 16
#define BLOCK 256
// 2-wide threads: 32 batches * 32 y-strips * 256 x-strips = 262144 threads
#define TOTAL_THREADS (NBATCH * (IMG_H / RSTRIP) * (IMG_W / 2))
#define NBLOCKS (TOTAL_THREADS / BLOCK)   // 1024
#define NPIX ((long long)NBATCH * IMG_H * IMG_W)

__device__ float2 g_partials[NBLOCKS];
__device__ unsigned int g_ticket = 0;     // reset by the last block each call

// Main-body float2 load.
__device__ __forceinline__ float2 load2(const float* __restrict__ img, int y, int x0) {
    if ((unsigned)y < IMG_H)
        return __ldg(reinterpret_cast<const float2*>(img + (size_t)y * IMG_W + x0));
    return make_float2(0.f, 0.f);
}

// Assemble 4-wide raw row (2 px + 2 halo scalars). Halo lines were pulled by
// this warp's own float2s an iteration earlier -> L1 hits.
__device__ __forceinline__ void assemble(const float* __restrict__ img, int y, int x0,
                                         float2 m, float v[4]) {
    v[1] = m.x; v[2] = m.y;
    if ((unsigned)y < IMG_H) {
        const float* row = img + (size_t)y * IMG_W;
        v[0] = (x0 > 0)         ? __ldg(row + x0 - 1) : 0.f;
        v[3] = (x0 + 2 < IMG_W) ? __ldg(row + x0 + 2) : 0.f;
    } else {
        v[0] = 0.f; v[3] = 0.f;
    }
}

// Sobel |Gx|+|Gy| for 2 px from 3 raw 4-wide rows (column-sum form).
__device__ __forceinline__ void sobel2(const float r0[4], const float r1[4],
                                       const float r2[4], float s[2]) {
    float c[4], d[4];
#pragma unroll
    for (int j = 0; j < 4; ++j) {
        c[j] = r0[j] + 2.f * r1[j] + r2[j];   // vertical [1,2,1]
        d[j] = r0[j] - r2[j];                 // vertical [1,0,-1]
    }
#pragma unroll
    for (int j = 0; j < 2; ++j) {
        float gx = c[j + 2] - c[j];                       // horiz [-1,0,1]
        float gy = d[j] + 2.f * d[j + 1] + d[j + 2];      // horiz [1,2,1]
        s[j] = fabsf(gx) + fabsf(gy);
    }
}

__global__ __launch_bounds__(BLOCK, 3)   // 3 blocks/SM -> 24 warps (issue-bound fix)
void fuse_main(const float* __restrict__ A, const float* __restrict__ Bi,
               const float* __restrict__ F, const int* __restrict__ scheme,
               float* __restrict__ out) {
    int t   = blockIdx.x * BLOCK + threadIdx.x;
    int b   = t >> 13;          // 8192 strips per image (32 ys * 256 xs)
    int rem = t & 8191;
    int ys  = rem >> 8;         // 32 y-strips
    int xs  = rem & 255;        // 256 x-strips
    int x0  = xs << 1;
    int y0  = ys * RSTRIP;

    size_t off = (size_t)b * IMG_H * IMG_W;
    const float* pA = A  + off;
    const float* pB = Bi + off;
    const float* pF = F  + off;
    // JAX default x64-disabled: fuse_scheme materializes as int32
    const bool avg = (scheme[b] == 0);

    // Raw-row rings: 3 rows x 4 floats x 3 images = 36 regs.
    float rvA[3][4], rvB[3][4], rvF[3][4];
    float sumL = 0.f, sumG = 0.f;

    // Depth-2 float2 prefetch pipeline (12 regs).
    float2 cA = load2(pA, y0 - 1, x0);
    float2 cB = load2(pB, y0 - 1, x0);
    float2 cF = load2(pF, y0 - 1, x0);
    float2 nA = load2(pA, y0,     x0);
    float2 nB = load2(pB, y0,     x0);
    float2 nF = load2(pF, y0,     x0);

#pragma unroll
    for (int i = 0; i < RSTRIP + 2; ++i) {
        int y = y0 - 1 + i;

        // 1) Issue row i+2 loads first; no consumer for 2 iterations.
        float2 tA, tB, tF;
        if (i + 2 < RSTRIP + 2) {
            tA = load2(pA, y + 2, x0);
            tB = load2(pB, y + 2, x0);
            tF = load2(pF, y + 2, x0);
        }

        // 2) Assemble current row into the ring (halo scalars = L1 hits).
        int cur = i % 3;
        assemble(pA, y, x0, cA, rvA[cur]);
        assemble(pB, y, x0, cB, rvB[cur]);
        assemble(pF, y, x0, cF, rvF[cur]);

        // l_loss contribution: rows y0 .. y0+R-1  (i in [1, R])
        if (i >= 1 && i <= RSTRIP) {
#pragma unroll
            for (int j = 0; j < 2; ++j) {
                float ab = avg ? 0.5f * (rvA[cur][j + 1] + rvB[cur][j + 1])
                               : fmaxf(rvA[cur][j + 1], rvB[cur][j + 1]);
                sumL += fabsf(ab - rvF[cur][j + 1]);
            }
        }

        // grad_loss for output row y-1 once rows i-2, i-1, i are resident
        if (i >= 2) {
            int r0 = (i - 2) % 3, r1 = (i - 1) % 3;
            float sA[2], sB[2], sF[2];
            sobel2(rvA[r0], rvA[r1], rvA[cur], sA);
            sobel2(rvB[r0], rvB[r1], rvB[cur], sB);
            sobel2(rvF[r0], rvF[r1], rvF[cur], sF);
#pragma unroll
            for (int j = 0; j < 2; ++j)
                sumG += fabsf(sF[j] - fmaxf(sA[j], sB[j]));
        }

        // 3) Rotate the prefetch pipeline.
        cA = nA; cB = nB; cF = nF;
        nA = tA; nB = tB; nF = tF;
    }

    // ---- Block reduction (deterministic, no float atomics) ----
#pragma unroll
    for (int o = 16; o > 0; o >>= 1) {
        sumL += __shfl_down_sync(0xffffffffu, sumL, o);
        sumG += __shfl_down_sync(0xffffffffu, sumG, o);
    }
    __shared__ float sL[BLOCK / 32], sG[BLOCK / 32];
    __shared__ bool s_last;
    int lane = threadIdx.x & 31, wid = threadIdx.x >> 5;
    if (lane == 0) { sL[wid] = sumL; sG[wid] = sumG; }
    __syncthreads();
    if (threadIdx.x == 0) {
        float l = 0.f, g = 0.f;
#pragma unroll
        for (int k = 0; k < BLOCK / 32; ++k) { l += sL[k]; g += sG[k]; }
        g_partials[blockIdx.x] = make_float2(l, g);
        __threadfence();
        unsigned int ticket = atomicAdd(&g_ticket, 1u);
        s_last = (ticket == NBLOCKS - 1);
    }
    __syncthreads();

    // ---- Last block finalizes: fixed-order sum over all partials ----
    if (s_last) {
        float l = 0.f, g = 0.f;
#pragma unroll
        for (int k = 0; k < NBLOCKS / BLOCK; ++k) {
            float2 p = g_partials[threadIdx.x + k * BLOCK];
            l += p.x; g += p.y;
        }
#pragma unroll
        for (int o = 16; o > 0; o >>= 1) {
            l += __shfl_down_sync(0xffffffffu, l, o);
            g += __shfl_down_sync(0xffffffffu, g, o);
        }
        if (lane == 0) { sL[wid] = l; sG[wid] = g; }
        __syncthreads();
        if (threadIdx.x == 0) {
            float L = 0.f, G = 0.f;
#pragma unroll
            for (int k = 0; k < BLOCK / 32; ++k) { L += sL[k]; G += sG[k]; }
            out[0] = (L + G) * (1.0f / (float)NPIX);  // l_loss + grad_loss; 0.0*cs_loss dropped
            g_ticket = 0;   // reset for next graph replay
        }
    }
}

extern "C" void kernel_launch(void* const* d_in, const int* in_sizes, int n_in,
                              void* d_out, int out_size) {
    (void)in_sizes; (void)n_in; (void)out_size;
    const float* A      = (const float*)d_in[0];
    const float* B      = (const float*)d_in[1];
    const float* F      = (const float*)d_in[2];
    const int*   scheme = (const int*)d_in[3];
    float* out = (float*)d_out;

    fuse_main<<<NBLOCKS, BLOCK>>>(A, B, F, scheme, out);
}